// round 2
// baseline (speedup 1.0000x reference)
#include <cuda_runtime.h>
#include <cstdint>
#include <cstddef>

#define Bn 16
#define Tn 1024
#define DIN 4608
#define DRED 128
#define Hn 32
#define G3 96
#define TAUc 12

// Scratch (no dynamic allocation allowed)
__device__ float g_Wc[G3 * DIN];          // combined weight w_ih @ w_dr  [96,4608]
__device__ float g_bc[G3];                // combined bias (incl. b_hh for r,z gates)
__device__ float g_gi[Bn * Tn * G3];      // input gates for all timesteps
__device__ float g_hs[Bn * Tn * Hn];      // GRU hidden states

typedef unsigned long long ull;

__device__ __forceinline__ ull fma2(ull a, ull b, ull c) {
    ull d;
    asm("fma.rn.f32x2 %0, %1, %2, %3;" : "=l"(d) : "l"(a), "l"(b), "l"(c));
    return d;
}
__device__ __forceinline__ ull add2(ull a, ull b) {
    ull d;
    asm("add.rn.f32x2 %0, %1, %2;" : "=l"(d) : "l"(a), "l"(b));
    return d;
}
__device__ __forceinline__ ull pack2(float x) {
    ull d;
    asm("mov.b64 %0, {%1, %1};" : "=l"(d) : "f"(x));
    return d;
}
__device__ __forceinline__ ull packab(float a, float b) {
    ull d;
    asm("mov.b64 %0, {%1, %2};" : "=l"(d) : "f"(a), "f"(b));
    return d;
}
__device__ __forceinline__ float2 unpack2(ull v) {
    float2 f;
    asm("mov.b64 {%0, %1}, %2;" : "=f"(f.x), "=f"(f.y) : "l"(v));
    return f;
}
__device__ __forceinline__ float tanhapx(float x) {
    float y;
    asm("tanh.approx.f32 %0, %1;" : "=f"(y) : "f"(x));
    return y;
}
// sigmoid(x) = 0.5*tanh(0.5x) + 0.5  (1 MUFU instead of EX2+RCP chain)
__device__ __forceinline__ float sigmfast(float x) {
    return fmaf(0.5f, tanhapx(0.5f * x), 0.5f);
}

// ---------------------------------------------------------------------------
// Kernel A: W_comb[g][d] = sum_r w_ih[g][r] * w_dr[r][d]
// ---------------------------------------------------------------------------
__global__ void k_wcomb(const float* __restrict__ w_ih, const float* __restrict__ w_dr) {
    __shared__ float swt[DRED][48];   // [r][gg]
    const int gbase = blockIdx.y * 48;
    for (int idx = threadIdx.x; idx < DRED * 48; idx += 128) {
        int r = idx / 48, gg = idx % 48;
        swt[r][gg] = w_ih[(gbase + gg) * DRED + r];
    }
    __syncthreads();
    const int d = blockIdx.x * 128 + threadIdx.x;
    float acc[48];
#pragma unroll
    for (int gg = 0; gg < 48; gg++) acc[gg] = 0.f;
#pragma unroll 4
    for (int r = 0; r < DRED; r++) {
        float a = w_dr[r * DIN + d];
#pragma unroll
        for (int gg = 0; gg < 48; gg++) acc[gg] = fmaf(swt[r][gg], a, acc[gg]);
    }
    for (int gg = 0; gg < 48; gg++) g_Wc[(size_t)(gbase + gg) * DIN + d] = acc[gg];
}

// b_comb[g] = b_ih[g] + sum_r w_ih[g][r] * b_dr[r]  (+ b_hh[g] for r,z gates)
__global__ void k_bcomb(const float* __restrict__ w_ih, const float* __restrict__ b_dr,
                        const float* __restrict__ b_ih, const float* __restrict__ b_hh) {
    int g = threadIdx.x;
    if (g < G3) {
        float acc = b_ih[g] + (g < 64 ? b_hh[g] : 0.f);
        for (int r = 0; r < DRED; r++) acc = fmaf(w_ih[g * DRED + r], b_dr[r], acc);
        g_bc[g] = acc;
    }
}

// ---------------------------------------------------------------------------
// Kernel B: gi[M=16384, N=96] = x[M, 4608] @ W_comb^T + b_comb
// ---------------------------------------------------------------------------
__global__ __launch_bounds__(256) void k_gemm(const float* __restrict__ x) {
    __shared__ float As[32][68];   // [k][m], padded
    __shared__ float Bs[32][98];   // [k][n], padded

    const int tid = threadIdx.x;
    const int m0 = blockIdx.x * 64;
    const int lrow = tid >> 3, lc4 = tid & 7;
    const int ty = tid >> 4, tx = tid & 15;

    ull acc[4][3];
#pragma unroll
    for (int i = 0; i < 4; i++)
#pragma unroll
        for (int p = 0; p < 3; p++) acc[i][p] = 0ull;

    for (int k0 = 0; k0 < DIN; k0 += 32) {
#pragma unroll
        for (int p = 0; p < 2; p++) {
            int r = lrow + 32 * p;
            float4 v = *(const float4*)&x[(size_t)(m0 + r) * DIN + k0 + lc4 * 4];
            As[lc4 * 4 + 0][r] = v.x; As[lc4 * 4 + 1][r] = v.y;
            As[lc4 * 4 + 2][r] = v.z; As[lc4 * 4 + 3][r] = v.w;
        }
#pragma unroll
        for (int p = 0; p < 3; p++) {
            int n = lrow + 32 * p;
            float4 v = *(const float4*)&g_Wc[(size_t)n * DIN + k0 + lc4 * 4];
            Bs[lc4 * 4 + 0][n] = v.x; Bs[lc4 * 4 + 1][n] = v.y;
            Bs[lc4 * 4 + 2][n] = v.z; Bs[lc4 * 4 + 3][n] = v.w;
        }
        __syncthreads();
#pragma unroll
        for (int kk = 0; kk < 32; kk++) {
            float4 a = *(const float4*)&As[kk][ty * 4];
            const ull* bp = (const ull*)&Bs[kk][tx * 6];
            ull b0 = bp[0], b1 = bp[1], b2 = bp[2];
            ull A0 = pack2(a.x), A1 = pack2(a.y), A2 = pack2(a.z), A3 = pack2(a.w);
            acc[0][0] = fma2(A0, b0, acc[0][0]); acc[0][1] = fma2(A0, b1, acc[0][1]); acc[0][2] = fma2(A0, b2, acc[0][2]);
            acc[1][0] = fma2(A1, b0, acc[1][0]); acc[1][1] = fma2(A1, b1, acc[1][1]); acc[1][2] = fma2(A1, b2, acc[1][2]);
            acc[2][0] = fma2(A2, b0, acc[2][0]); acc[2][1] = fma2(A2, b1, acc[2][1]); acc[2][2] = fma2(A2, b2, acc[2][2]);
            acc[3][0] = fma2(A3, b0, acc[3][0]); acc[3][1] = fma2(A3, b1, acc[3][1]); acc[3][2] = fma2(A3, b2, acc[3][2]);
        }
        __syncthreads();
    }

    ull bias[3];
    {
        const ull* bb = (const ull*)&g_bc[tx * 6];
        bias[0] = bb[0]; bias[1] = bb[1]; bias[2] = bb[2];
    }
#pragma unroll
    for (int i = 0; i < 4; i++) {
        size_t row = (size_t)(m0 + ty * 4 + i) * G3 + tx * 6;
        ull* op = (ull*)&g_gi[row];
        op[0] = add2(acc[i][0], bias[0]);
        op[1] = add2(acc[i][1], bias[1]);
        op[2] = add2(acc[i][2], bias[2]);
    }
}

// ---------------------------------------------------------------------------
// Kernel C: GRU recurrence — ONE WARP PER BATCH. Lane j owns h_j and gate
// rows j / 32+j / 64+j. No shared memory, no barriers: h broadcast via
// 64-bit shuffles of adjacent-pair packs, dot products in f32x2.
// ---------------------------------------------------------------------------
__global__ __launch_bounds__(32) void k_gru(const float* __restrict__ w_hh,
                                            const float* __restrict__ b_hh) {
    const int b = blockIdx.x, j = threadIdx.x;

    // Pack weight rows along k: wr[k] = (w_hh[j][2k], w_hh[j][2k+1]) etc.
    ull wr[16], wz[16], wn[16];
#pragma unroll
    for (int i = 0; i < 8; i++) {
        float4 vr = ((const float4*)(w_hh + (size_t)j * Hn))[i];
        float4 vz = ((const float4*)(w_hh + (size_t)(Hn + j) * Hn))[i];
        float4 vn = ((const float4*)(w_hh + (size_t)(2 * Hn + j) * Hn))[i];
        wr[2 * i] = packab(vr.x, vr.y); wr[2 * i + 1] = packab(vr.z, vr.w);
        wz[2 * i] = packab(vz.x, vz.y); wz[2 * i + 1] = packab(vz.z, vz.w);
        wn[2 * i] = packab(vn.x, vn.y); wn[2 * i + 1] = packab(vn.z, vn.w);
    }
    const float bn = b_hh[2 * Hn + j];   // b_hh for r,z already folded into gi

    const float* __restrict__ gip = g_gi + (size_t)b * Tn * G3;
    float* __restrict__ hsp = g_hs + (size_t)b * Tn * Hn;

    float h = 0.f;
    ull hp = 0ull;                        // (h_j, h_{j+1}) pack

    // depth-2 gi prefetch (g_gi is L2-resident right after the GEMM)
    float pr[2], pz[2], pn[2];
    pr[0] = gip[j];            pz[0] = gip[Hn + j];            pn[0] = gip[2 * Hn + j];
    pr[1] = gip[G3 + j];       pz[1] = gip[G3 + Hn + j];       pn[1] = gip[G3 + 2 * Hn + j];

#pragma unroll 2
    for (int t = 0; t < Tn; t++) {
        const int slot = t & 1;
        ull ar2 = 0ull, az2 = 0ull, an2 = 0ull;
#pragma unroll
        for (int k = 0; k < 16; k++) {
            long long hk = __shfl_sync(0xffffffffu, (long long)hp, 2 * k);
            ar2 = fma2(wr[k], (ull)hk, ar2);
            az2 = fma2(wz[k], (ull)hk, az2);
            an2 = fma2(wn[k], (ull)hk, an2);
        }
        float2 fr = unpack2(ar2), fz = unpack2(az2), fn = unpack2(an2);
        float r = sigmfast(pr[slot] + (fr.x + fr.y));
        float z = sigmfast(pz[slot] + (fz.x + fz.y));
        float n = tanhapx(fmaf(r, (fn.x + fn.y) + bn, pn[slot]));
        h = fmaf(z, h - n, n);            // (1-z)*n + z*h
        hsp[t * Hn + j] = h;

        // rebuild adjacent-pair pack for next step's broadcasts
        float hdn = __shfl_down_sync(0xffffffffu, h, 1);
        hp = packab(h, hdn);

        if (t + 2 < Tn) {
            const float* p2 = gip + (size_t)(t + 2) * G3;
            pr[slot] = p2[j]; pz[slot] = p2[Hn + j]; pn[slot] = p2[2 * Hn + j];
        }
    }
}

// ---------------------------------------------------------------------------
// Kernel D: quality head + pooling + masked mean + output heads.
// ---------------------------------------------------------------------------
__global__ __launch_bounds__(256) void k_pool(const int* __restrict__ x_len,
    const float* __restrict__ w_reg, const float* __restrict__ b_reg,
    const float* __restrict__ w_nlm1, const float* __restrict__ b_nlm1,
    const float* __restrict__ w_nlm2, const float* __restrict__ b_nlm2,
    const float* __restrict__ w_lm, const float* __restrict__ b_lm,
    float* __restrict__ out)
{
    __shared__ float sq[Tn];
    __shared__ float red[256];
    __shared__ float swr[Hn];
    const int b = blockIdx.x, tid = threadIdx.x;
    if (tid < Hn) swr[tid] = w_reg[tid];
    __syncthreads();
    const float breg = b_reg[0];

    for (int t = tid; t < Tn; t += 256) {
        const float4* hr = (const float4*)(g_hs + ((size_t)b * Tn + t) * Hn);
        float acc = breg;
#pragma unroll
        for (int i = 0; i < 8; i++) {
            float4 v = hr[i];
            acc += v.x * swr[4 * i] + v.y * swr[4 * i + 1] + v.z * swr[4 * i + 2] + v.w * swr[4 * i + 3];
        }
        sq[t] = acc;
    }
    __syncthreads();

    const int len = x_len[b];
    float local = 0.f;
    for (int t = tid; t < Tn; t += 256) {
        if (t < len) {
            float mn = sq[t];
#pragma unroll
            for (int k = 1; k < TAUc; k++) {
                int idx = t - k;
                float v = (idx >= 0) ? sq[idx] : 3.402823466e38f;
                mn = fminf(mn, v);
            }
            float num = 0.f, den = 0.f;
#pragma unroll
            for (int k = 0; k < TAUc; k++) {
                int idx = t + k;
                float v = (idx < len) ? sq[idx] : 1e4f;
                float e = __expf(-v);
                num = fmaf(v, e, num);
                den += e;
            }
            float m = num / den;
            local += 0.5f * m + 0.5f * mn;
        }
    }
    red[tid] = local;
    __syncthreads();
    for (int s = 128; s > 0; s >>= 1) {
        if (tid < s) red[tid] += red[tid + s];
        __syncthreads();
    }
    if (tid == 0) {
        float rel = red[0] / (float)len;
        float relative = 1.f / (1.f + expf(-rel));
        float mapped = (1.f / (1.f + expf(-(relative * w_nlm1[0] + b_nlm1[0])))) * w_nlm2[0] + b_nlm2[0];
        float aligned = mapped * w_lm[0] + b_lm[0];
        out[b] = relative;
        out[Bn + b] = mapped;
        out[2 * Bn + b] = aligned;
    }
}

extern "C" void kernel_launch(void* const* d_in, const int* in_sizes, int n_in,
                              void* d_out, int out_size) {
    const float* x      = (const float*)d_in[0];
    const int*   x_len  = (const int*)d_in[1];
    const float* w_dr   = (const float*)d_in[2];
    const float* b_dr   = (const float*)d_in[3];
    const float* w_ih   = (const float*)d_in[4];
    const float* w_hh   = (const float*)d_in[5];
    const float* b_ih   = (const float*)d_in[6];
    const float* b_hh   = (const float*)d_in[7];
    const float* w_reg  = (const float*)d_in[8];
    const float* b_reg  = (const float*)d_in[9];
    const float* w_nlm1 = (const float*)d_in[10];
    const float* b_nlm1 = (const float*)d_in[11];
    const float* w_nlm2 = (const float*)d_in[12];
    const float* b_nlm2 = (const float*)d_in[13];
    const float* w_lm   = (const float*)d_in[14];
    const float* b_lm   = (const float*)d_in[15];
    float* out = (float*)d_out;

    k_wcomb<<<dim3(36, 2), 128>>>(w_ih, w_dr);
    k_bcomb<<<1, 128>>>(w_ih, b_dr, b_ih, b_hh);
    k_gemm<<<256, 256>>>(x);
    k_gru<<<16, 32>>>(w_hh, b_hh);
    k_pool<<<16, 256>>>(x_len, w_reg, b_reg, w_nlm1, b_nlm1, w_nlm2, b_nlm2, w_lm, b_lm, out);
}

// round 5
// speedup vs baseline: 1.8699x; 1.8699x over previous
#include <cuda_runtime.h>
#include <cstdint>
#include <cstddef>

#define Bn 16
#define Tn 1024
#define DIN 4608
#define DRED 128
#define Hn 32
#define G3 96
#define TAUc 12

// ---- mma.sync tf32 GEMM tiling ----
#define TILE_M 128
#define KCH 16
#define NCH (DIN / KCH)          // 288
#define APAD 20                  // smem row stride in floats (conflict-free)

// Scratch (no dynamic allocation allowed)
__device__ float g_Wc[G3 * DIN];          // combined weight w_ih @ w_dr  [96,4608]
__device__ float g_bc[G3];                // combined bias (incl. b_hh for r,z gates)
__device__ float g_gi[Bn * Tn * G3];      // input gates for all timesteps
__device__ float g_hs[Bn * Tn * Hn];      // GRU hidden states

typedef unsigned long long ull;

__device__ __forceinline__ ull fma2(ull a, ull b, ull c) {
    ull d;
    asm("fma.rn.f32x2 %0, %1, %2, %3;" : "=l"(d) : "l"(a), "l"(b), "l"(c));
    return d;
}
__device__ __forceinline__ ull add2(ull a, ull b) {
    ull d;
    asm("add.rn.f32x2 %0, %1, %2;" : "=l"(d) : "l"(a), "l"(b));
    return d;
}
__device__ __forceinline__ ull packab(float a, float b) {
    ull d;
    asm("mov.b64 %0, {%1, %2};" : "=l"(d) : "f"(a), "f"(b));
    return d;
}
__device__ __forceinline__ float2 unpack2(ull v) {
    float2 f;
    asm("mov.b64 {%0, %1}, %2;" : "=f"(f.x), "=f"(f.y) : "l"(v));
    return f;
}
__device__ __forceinline__ float tanhapx(float x) {
    float y;
    asm("tanh.approx.f32 %0, %1;" : "=f"(y) : "f"(x));
    return y;
}
__device__ __forceinline__ float sigmfast(float x) {
    return fmaf(0.5f, tanhapx(0.5f * x), 0.5f);
}
__device__ __forceinline__ uint32_t smem_u32(const void* p) {
    uint32_t a;
    asm("{ .reg .u64 t; cvta.to.shared.u64 t, %1; cvt.u32.u64 %0, t; }" : "=r"(a) : "l"(p));
    return a;
}
__device__ __forceinline__ void cpa16(uint32_t dst, const void* src) {
    asm volatile("cp.async.cg.shared.global [%0], [%1], 16;"
                 :: "r"(dst), "l"(__cvta_generic_to_global(src)));
}
#define CP_COMMIT() asm volatile("cp.async.commit_group;" ::: "memory")
#define CP_WAIT1()  asm volatile("cp.async.wait_group 1;" ::: "memory")

__device__ __forceinline__ void mma_tf32(float& c0, float& c1, float& c2, float& c3,
                                         uint32_t a0, uint32_t a1, uint32_t a2, uint32_t a3,
                                         uint32_t b0, uint32_t b1) {
    asm volatile(
        "mma.sync.aligned.m16n8k8.row.col.f32.tf32.tf32.f32 "
        "{%0,%1,%2,%3}, {%4,%5,%6,%7}, {%8,%9}, {%0,%1,%2,%3};"
        : "+f"(c0), "+f"(c1), "+f"(c2), "+f"(c3)
        : "r"(a0), "r"(a1), "r"(a2), "r"(a3), "r"(b0), "r"(b1));
}

// ---------------------------------------------------------------------------
// Kernel A: W_comb[g][d] = sum_r w_ih[g][r] * w_dr[r][d]
// ---------------------------------------------------------------------------
__global__ void k_wcomb(const float* __restrict__ w_ih, const float* __restrict__ w_dr) {
    __shared__ float swt[DRED][48];
    const int gbase = blockIdx.y * 48;
    for (int idx = threadIdx.x; idx < DRED * 48; idx += 128) {
        int r = idx / 48, gg = idx % 48;
        swt[r][gg] = w_ih[(gbase + gg) * DRED + r];
    }
    __syncthreads();
    const int d = blockIdx.x * 128 + threadIdx.x;
    float acc[48];
#pragma unroll
    for (int gg = 0; gg < 48; gg++) acc[gg] = 0.f;
#pragma unroll 4
    for (int r = 0; r < DRED; r++) {
        float a = w_dr[r * DIN + d];
#pragma unroll
        for (int gg = 0; gg < 48; gg++) acc[gg] = fmaf(swt[r][gg], a, acc[gg]);
    }
    for (int gg = 0; gg < 48; gg++) g_Wc[(size_t)(gbase + gg) * DIN + d] = acc[gg];
}

// b_comb[g] = b_ih[g] + sum_r w_ih[g][r]*b_dr[r]  (+ b_hh[g] for r,z gates)
__global__ void k_bcomb(const float* __restrict__ w_ih, const float* __restrict__ b_dr,
                        const float* __restrict__ b_ih, const float* __restrict__ b_hh) {
    int g = threadIdx.x;
    if (g < G3) {
        float acc = b_ih[g] + (g < 64 ? b_hh[g] : 0.f);
        for (int r = 0; r < DRED; r++) acc = fmaf(w_ih[g * DRED + r], b_dr[r], acc);
        g_bc[g] = acc;
    }
}

// ---------------------------------------------------------------------------
// Kernel B: mma.sync tf32 GEMM  gi[16384,96] = x[16384,4608] @ Wc^T + b_comb
// 128 CTAs x 256 threads (8 warps); warp w owns rows w*16..w*16+15, all 96 cols.
// 2-stage cp.async pipeline, padded smem (stride 20 -> conflict-free frags).
// ---------------------------------------------------------------------------
__global__ __launch_bounds__(256) void k_gemm_mma(const float* __restrict__ x) {
    __shared__ float sA[2][TILE_M][APAD];
    __shared__ float sB[2][G3][APAD];
    __shared__ float sbias[G3];

    const int tid = threadIdx.x;
    const int wid = tid >> 5, lane = tid & 31;
    const int g = lane >> 2, tig = lane & 3;
    const int wm = wid * 16;
    const int m0 = blockIdx.x * TILE_M;

    if (tid < G3) sbias[tid] = g_bc[tid];

    // loader: chunk kc -> stage s
    auto load_chunk = [&](int kc, int s) {
        const float* xa = x + (size_t)m0 * DIN + kc * KCH;
        const float* wb = g_Wc + (size_t)kc * KCH;
        // A: 512 float4, 2 per thread
#pragma unroll
        for (int p = 0; p < 2; p++) {
            int idx = tid + 256 * p;
            int row = idx >> 2, c4 = idx & 3;
            cpa16(smem_u32(&sA[s][row][c4 * 4]), xa + (size_t)row * DIN + c4 * 4);
        }
        // B: 384 float4
        {
            int idx = tid;
            if (idx < 256) {
                int row = idx >> 2, c4 = idx & 3;
                cpa16(smem_u32(&sB[s][row][c4 * 4]), wb + (size_t)row * DIN + c4 * 4);
            }
            idx = 256 + tid;
            if (tid < 128) {
                int row = idx >> 2, c4 = idx & 3;
                cpa16(smem_u32(&sB[s][row][c4 * 4]), wb + (size_t)row * DIN + c4 * 4);
            }
        }
    };

    float acc[12][4];
#pragma unroll
    for (int j = 0; j < 12; j++)
#pragma unroll
        for (int q = 0; q < 4; q++) acc[j][q] = 0.f;

    load_chunk(0, 0); CP_COMMIT();
    load_chunk(1, 1); CP_COMMIT();

    for (int kc = 0; kc < NCH; kc++) {
        const int s = kc & 1;
        CP_WAIT1();            // chunk kc landed
        __syncthreads();

#pragma unroll
        for (int kk = 0; kk < KCH; kk += 8) {
            uint32_t a0 = __float_as_uint(sA[s][wm + g][kk + tig]);
            uint32_t a1 = __float_as_uint(sA[s][wm + g + 8][kk + tig]);
            uint32_t a2 = __float_as_uint(sA[s][wm + g][kk + tig + 4]);
            uint32_t a3 = __float_as_uint(sA[s][wm + g + 8][kk + tig + 4]);
#pragma unroll
            for (int j = 0; j < 12; j++) {
                uint32_t b0 = __float_as_uint(sB[s][j * 8 + g][kk + tig]);
                uint32_t b1 = __float_as_uint(sB[s][j * 8 + g][kk + tig + 4]);
                mma_tf32(acc[j][0], acc[j][1], acc[j][2], acc[j][3],
                         a0, a1, a2, a3, b0, b1);
            }
        }

        if (kc + 2 < NCH) {
            __syncthreads();               // all warps done reading stage s
            load_chunk(kc + 2, s);         // refill it
        }
        CP_COMMIT();                       // one group per iteration
    }

    // epilogue: C rows wm+g, wm+g+8; cols j*8 + 2*tig (+1)
    const int row0 = m0 + wm + g, row1 = row0 + 8;
#pragma unroll
    for (int j = 0; j < 12; j++) {
        int col = j * 8 + tig * 2;
        float2 v0 = make_float2(acc[j][0] + sbias[col], acc[j][1] + sbias[col + 1]);
        float2 v1 = make_float2(acc[j][2] + sbias[col], acc[j][3] + sbias[col + 1]);
        *(float2*)&g_gi[(size_t)row0 * G3 + col] = v0;
        *(float2*)&g_gi[(size_t)row1 * G3 + col] = v1;
    }
}

// ---------------------------------------------------------------------------
// Kernel C: GRU — one warp per batch; h broadcast via double-buffered smem
// (1 STS + 8 LDS.128 + 1 syncwarp per step; no shuffles, no block barriers).
// ---------------------------------------------------------------------------
__global__ __launch_bounds__(32) void k_gru(const float* __restrict__ w_hh,
                                            const float* __restrict__ b_hh) {
    __shared__ __align__(16) float hb[2][Hn];
    const int b = blockIdx.x, j = threadIdx.x;

    ull wr[16], wz[16], wn[16];
#pragma unroll
    for (int i = 0; i < 8; i++) {
        float4 vr = ((const float4*)(w_hh + (size_t)j * Hn))[i];
        float4 vz = ((const float4*)(w_hh + (size_t)(Hn + j) * Hn))[i];
        float4 vn = ((const float4*)(w_hh + (size_t)(2 * Hn + j) * Hn))[i];
        wr[2 * i] = packab(vr.x, vr.y); wr[2 * i + 1] = packab(vr.z, vr.w);
        wz[2 * i] = packab(vz.x, vz.y); wz[2 * i + 1] = packab(vz.z, vz.w);
        wn[2 * i] = packab(vn.x, vn.y); wn[2 * i + 1] = packab(vn.z, vn.w);
    }
    const float bn = b_hh[2 * Hn + j];

    const float* __restrict__ gip = g_gi + (size_t)b * Tn * G3;
    float* __restrict__ hsp = g_hs + (size_t)b * Tn * Hn;

    hb[0][j] = 0.f;
    __syncwarp();
    float h = 0.f;

    float pr[2], pz[2], pn[2];
    pr[0] = gip[j];      pz[0] = gip[Hn + j];      pn[0] = gip[2 * Hn + j];
    pr[1] = gip[G3 + j]; pz[1] = gip[G3 + Hn + j]; pn[1] = gip[G3 + 2 * Hn + j];

#pragma unroll 2
    for (int t = 0; t < Tn; t++) {
        const int slot = t & 1;
        const ulonglong2* hp = (const ulonglong2*)hb[t & 1];
        ull r0 = 0, r1 = 0, z0 = 0, z1 = 0, n0 = 0, n1 = 0;
#pragma unroll
        for (int i = 0; i < 8; i++) {
            ulonglong2 hv = hp[i];
            r0 = fma2(wr[2 * i], hv.x, r0); r1 = fma2(wr[2 * i + 1], hv.y, r1);
            z0 = fma2(wz[2 * i], hv.x, z0); z1 = fma2(wz[2 * i + 1], hv.y, z1);
            n0 = fma2(wn[2 * i], hv.x, n0); n1 = fma2(wn[2 * i + 1], hv.y, n1);
        }
        float2 fr = unpack2(add2(r0, r1));
        float2 fz = unpack2(add2(z0, z1));
        float2 fn = unpack2(add2(n0, n1));
        float r = sigmfast(pr[slot] + (fr.x + fr.y));
        float z = sigmfast(pz[slot] + (fz.x + fz.y));
        float n = tanhapx(fmaf(r, (fn.x + fn.y) + bn, pn[slot]));
        h = fmaf(z, h - n, n);
        hsp[t * Hn + j] = h;
        hb[(t + 1) & 1][j] = h;
        __syncwarp();
        if (t + 2 < Tn) {
            const float* p2 = gip + (size_t)(t + 2) * G3;
            pr[slot] = p2[j]; pz[slot] = p2[Hn + j]; pn[slot] = p2[2 * Hn + j];
        }
    }
}

// ---------------------------------------------------------------------------
// Kernel D: quality head + pooling + masked mean + output heads.
// ---------------------------------------------------------------------------
__global__ __launch_bounds__(256) void k_pool(const int* __restrict__ x_len,
    const float* __restrict__ w_reg, const float* __restrict__ b_reg,
    const float* __restrict__ w_nlm1, const float* __restrict__ b_nlm1,
    const float* __restrict__ w_nlm2, const float* __restrict__ b_nlm2,
    const float* __restrict__ w_lm, const float* __restrict__ b_lm,
    float* __restrict__ out)
{
    __shared__ float sq[Tn];
    __shared__ float red[256];
    __shared__ float swr[Hn];
    const int b = blockIdx.x, tid = threadIdx.x;
    if (tid < Hn) swr[tid] = w_reg[tid];
    __syncthreads();
    const float breg = b_reg[0];

    for (int t = tid; t < Tn; t += 256) {
        const float4* hr = (const float4*)(g_hs + ((size_t)b * Tn + t) * Hn);
        float acc = breg;
#pragma unroll
        for (int i = 0; i < 8; i++) {
            float4 v = hr[i];
            acc += v.x * swr[4 * i] + v.y * swr[4 * i + 1] + v.z * swr[4 * i + 2] + v.w * swr[4 * i + 3];
        }
        sq[t] = acc;
    }
    __syncthreads();

    const int len = x_len[b];
    float local = 0.f;
    for (int t = tid; t < Tn; t += 256) {
        if (t < len) {
            float mn = sq[t];
#pragma unroll
            for (int k = 1; k < TAUc; k++) {
                int idx = t - k;
                float v = (idx >= 0) ? sq[idx] : 3.402823466e38f;
                mn = fminf(mn, v);
            }
            float num = 0.f, den = 0.f;
#pragma unroll
            for (int k = 0; k < TAUc; k++) {
                int idx = t + k;
                float v = (idx < len) ? sq[idx] : 1e4f;
                float e = __expf(-v);
                num = fmaf(v, e, num);
                den += e;
            }
            float m = num / den;
            local += 0.5f * m + 0.5f * mn;
        }
    }
    red[tid] = local;
    __syncthreads();
    for (int s = 128; s > 0; s >>= 1) {
        if (tid < s) red[tid] += red[tid + s];
        __syncthreads();
    }
    if (tid == 0) {
        float rel = red[0] / (float)len;
        float relative = 1.f / (1.f + expf(-rel));
        float mapped = (1.f / (1.f + expf(-(relative * w_nlm1[0] + b_nlm1[0])))) * w_nlm2[0] + b_nlm2[0];
        float aligned = mapped * w_lm[0] + b_lm[0];
        out[b] = relative;
        out[Bn + b] = mapped;
        out[2 * Bn + b] = aligned;
    }
}

extern "C" void kernel_launch(void* const* d_in, const int* in_sizes, int n_in,
                              void* d_out, int out_size) {
    const float* x      = (const float*)d_in[0];
    const int*   x_len  = (const int*)d_in[1];
    const float* w_dr   = (const float*)d_in[2];
    const float* b_dr   = (const float*)d_in[3];
    const float* w_ih   = (const float*)d_in[4];
    const float* w_hh   = (const float*)d_in[5];
    const float* b_ih   = (const float*)d_in[6];
    const float* b_hh   = (const float*)d_in[7];
    const float* w_reg  = (const float*)d_in[8];
    const float* b_reg  = (const float*)d_in[9];
    const float* w_nlm1 = (const float*)d_in[10];
    const float* b_nlm1 = (const float*)d_in[11];
    const float* w_nlm2 = (const float*)d_in[12];
    const float* b_nlm2 = (const float*)d_in[13];
    const float* w_lm   = (const float*)d_in[14];
    const float* b_lm   = (const float*)d_in[15];
    float* out = (float*)d_out;

    k_wcomb<<<dim3(36, 2), 128>>>(w_ih, w_dr);
    k_bcomb<<<1, 128>>>(w_ih, b_dr, b_ih, b_hh);
    k_gemm_mma<<<128, 256>>>(x);
    k_gru<<<16, 32>>>(w_hh, b_hh);
    k_pool<<<16, 256>>>(x_len, w_reg, b_reg, w_nlm1, b_nlm1, w_nlm2, b_nlm2, w_lm, b_lm, out);
}